// round 16
// baseline (speedup 1.0000x reference)
#include <cuda_runtime.h>
#include <cuda_fp16.h>
#include <stdint.h>
#include <math.h>

#define TT 512
#define BB 256
#define FF 512
#define HH 512
#define NCTA 128
#define PH 1040
#define HSZ (64 * PH)              // 66560 h tile
#define XT_OFF HSZ                 // 66560 x tile (full K, same pitch)
#define GXR_OFF (XT_OFF + HSZ)     // 133120
#define GXSLOT 17408               // 64*68*4
#define SMEM_TOTAL (GXR_OFF + 2 * GXSLOT)   // 167936

// W (fp16) in mma-fragment order: [mt 32][wm 4][kstep 64][lane 32] x uint4
__device__ uint4 g_Wf[32 * 4 * 64 * 32];
// x pre-converted fp16, chunk blocks: [t][nt][kc][64r][64c] (8KB/blk)
__device__ uint8_t g_xs[512L * 4 * 8 * 8192];
__device__ __half g_h[2][BB * HH];
__device__ unsigned g_flag[4][32];   // [nt][mt]: steps completed

__device__ __forceinline__ uint32_t smem_u32(const void* p) {
    uint32_t a;
    asm("{ .reg .u64 t; cvta.to.shared.u64 t, %1; cvt.u32.u64 %0, t; }" : "=r"(a) : "l"(p));
    return a;
}
__device__ __forceinline__ unsigned pack2h(float a, float b) {
    __half2 t; t.x = __float2half_rn(a); t.y = __float2half_rn(b);
    return *(unsigned*)&t;
}
__device__ __forceinline__ float sig_fast(float v) {
    return __fdividef(1.0f, 1.0f + __expf(-v));
}
__device__ __forceinline__ float tanh_fast(float v) {
    float e = __expf(-2.0f * fabsf(v));
    return copysignf(__fdividef(1.0f - e, 1.0f + e), v);
}

#define MMA(c, a, b0, b1) \
    asm volatile("mma.sync.aligned.m16n8k16.row.col.f32.f16.f16.f32 " \
        "{%0,%1,%2,%3}, {%4,%5,%6,%7}, {%8,%9}, {%0,%1,%2,%3};" \
        : "+f"((c)[0]), "+f"((c)[1]), "+f"((c)[2]), "+f"((c)[3]) \
        : "r"((a).x), "r"((a).y), "r"((a).z), "r"((a).w), "r"(b0), "r"(b1))

#define CPASYNC16(dst, src) \
    asm volatile("cp.async.cg.shared.global [%0], [%1], 16;" :: "r"(dst), "l"(src))
#define CPCOMMIT() asm volatile("cp.async.commit_group;" ::: "memory")
#define CPWAIT(n)  asm volatile("cp.async.wait_group %0;" :: "n"(n) : "memory")
#define BAR(id)    asm volatile("bar.sync %0, 256;" :: "r"(id) : "memory")

// ---- phase 0: W gather to fp16 fragment order; zero h0; reset flags ----
__global__ void phase0(const float* __restrict__ wih, const float* __restrict__ whh) {
    long id = (long)blockIdx.x * blockDim.x + threadIdx.x;
    long stride = (long)gridDim.x * blockDim.x;
    for (long i = id; i < 32L * 4 * 64 * 32; i += stride) {
        int lane = (int)(i & 31);
        int kstep = (int)((i >> 5) & 63);
        int wm = (int)((i >> 11) & 3);
        int mt = (int)(i >> 13);
        int g = lane >> 2, c4 = lane & 3;
        int ka = kstep * 16 + 2 * c4;
        float e[2][4];
        #pragma unroll
        for (int rr = 0; rr < 2; ++rr) {
            int r = wm * 16 + g + rr * 8;
            int orig = (r >> 4) * 512 + mt * 16 + (r & 15);
            #pragma unroll
            for (int kk = 0; kk < 4; ++kk) {
                int k = ka + (kk & 1) + (kk >> 1) * 8;
                e[rr][kk] = (k < 512) ? wih[(long)orig * 512 + k]
                                      : whh[(long)orig * 512 + k - 512];
            }
        }
        uint4 o;
        o.x = pack2h(e[0][0], e[0][1]);
        o.y = pack2h(e[1][0], e[1][1]);
        o.z = pack2h(e[0][2], e[0][3]);
        o.w = pack2h(e[1][2], e[1][3]);
        g_Wf[i] = o;
    }
    __half z = __float2half_rn(0.0f);
    for (long i = id; i < (long)BB * HH; i += stride) g_h[0][i] = z;
    if (id < 128) ((unsigned*)g_flag)[id] = 0;
}

// ---- phase X: x -> fp16 chunk blocks ----
// id bits: k8[0:3) r[3:9) kc[9:12) nt[12:14) t[14:...)
__global__ void phaseX(const float* __restrict__ x) {
    long stride = (long)gridDim.x * blockDim.x;
    for (long id = (long)blockIdx.x * blockDim.x + threadIdx.x;
         id < 8388608L; id += stride) {
        int k8 = (int)(id & 7);
        int r  = (int)((id >> 3) & 63);
        int kc = (int)((id >> 9) & 7);
        int nt = (int)((id >> 12) & 3);
        long t = id >> 14;
        const float* src = x + ((t * 256) + nt * 64 + r) * 512L + kc * 64 + k8 * 8;
        float4 a = *(const float4*)src;
        float4 b = *(const float4*)(src + 4);
        uint4 hi = make_uint4(pack2h(a.x, a.y), pack2h(a.z, a.w),
                              pack2h(b.x, b.y), pack2h(b.z, b.w));
        long blk = (t * 4 + nt) * 8 + kc;
        *(uint4*)(g_xs + blk * 8192 + r * 128 + k8 * 16) = hi;
    }
}

// ---- fused persistent kernel: warps 0-7 recurrence, warps 8-15 gx producer ----
__global__ void __launch_bounds__(512, 1) lstm_fused(
    const float* __restrict__ bih,
    const float* __restrict__ bhh,
    float* __restrict__ out)
{
    extern __shared__ __align__(16) char sm[];
    __shared__ unsigned sR, sC;

    const int tid = threadIdx.x;
    const int mt = blockIdx.x >> 2;
    const int nt = blockIdx.x & 3;
    const int b0 = nt * 64;

    if (tid == 0) { sR = 0; sC = 0; }
    __syncthreads();

    if (tid >= 256) {
        // ================= PRODUCER: gx[t] = x_t * Wih^T + biases =================
        const int ptid = tid - 256;
        const int lane = ptid & 31;
        const int g = lane >> 2, c4 = lane & 3;
        const int wid = ptid >> 5;
        const int wm = wid >> 1, wn = wid & 1;
        const int nb = wn * 32;
        const uint4* __restrict__ wf = g_Wf + (long)(mt * 4 + wm) * 64 * 32;
        const uint32_t xtb = smem_u32(sm) + XT_OFF;

        const int r0 = wm * 16 + g, r1 = r0 + 8;
        const int o0 = (r0 >> 4) * 512 + mt * 16 + (r0 & 15);
        const int o1 = (r1 >> 4) * 512 + mt * 16 + (r1 & 15);
        const float b_r0 = bih[o0] + bhh[o0];
        const float b_r1 = bih[o1] + bhh[o1];

        for (int t = 0; t < TT; ++t) {
            // gq slot free AND prior-step x-tile reads complete (same BAR)
            if (ptid == 0) {
                volatile unsigned* c = &sC;
                while (*c + 2u <= (unsigned)t) { }
            }
            BAR(2);

            // stage full x tile: 8 chunks, 2 commit groups of 4 chunks
            const uint8_t* xb = g_xs + (((long)t * 4 + nt) * 8) * 8192;
            #pragma unroll
            for (int kc = 0; kc < 8; ++kc) {
                #pragma unroll
                for (int it = 0; it < 2; ++it) {
                    int i = ptid + it * 256;
                    int r = i >> 3, k8 = i & 7;
                    CPASYNC16(xtb + r * PH + kc * 128 + k8 * 16,
                              xb + kc * 8192 + r * 128 + k8 * 16);
                }
                if (kc == 3 || kc == 7) CPCOMMIT();
            }

            float acc[4][4];
            #pragma unroll
            for (int n2 = 0; n2 < 4; ++n2) {
                acc[n2][0] = b_r0; acc[n2][1] = b_r0;
                acc[n2][2] = b_r1; acc[n2][3] = b_r1;
            }

            #pragma unroll
            for (int half = 0; half < 2; ++half) {
                if (half == 0) CPWAIT(1); else CPWAIT(0);
                BAR(2);
                #pragma unroll
                for (int kc2 = 0; kc2 < 4; ++kc2) {
                    const int kc = half * 4 + kc2;
                    const uint4* wfb = wf + (long)(kc * 4) * 32;
                    #pragma unroll
                    for (int ks = 0; ks < 4; ++ks) {
                        uint4 Ah = __ldg(&wfb[ks * 32 + lane]);
                        const int koff = kc * 128 + ks * 32 + c4 * 4;
                        #pragma unroll
                        for (int n2 = 0; n2 < 4; ++n2) {
                            const int base = XT_OFF + (nb + n2 * 8 + g) * PH + koff;
                            unsigned bh0 = *(const unsigned*)(sm + base);
                            unsigned bh1 = *(const unsigned*)(sm + base + 16);
                            MMA(acc[n2], Ah, bh0, bh1);
                        }
                    }
                }
            }

            float* gq = (float*)(sm + GXR_OFF + (t & 1) * GXSLOT);
            #pragma unroll
            for (int n2 = 0; n2 < 4; ++n2) {
                const int col = nb + n2 * 8 + 2 * c4;
                const int row = wm * 16 + g;
                gq[row * 68 + col] = acc[n2][0];
                gq[row * 68 + col + 1] = acc[n2][1];
                gq[(row + 8) * 68 + col] = acc[n2][2];
                gq[(row + 8) * 68 + col + 1] = acc[n2][3];
            }
            BAR(2);
            if (ptid == 0) *(volatile unsigned*)&sR = (unsigned)(t + 1);
        }
    } else {
        // ================= CONSUMER: recurrence =================
        const int wid = tid >> 5;
        const int lane = tid & 31;
        const int g = lane >> 2, c4 = lane & 3;
        const int wm = wid >> 1, wn = wid & 1;
        const int nb = wn * 32;
        const uint4* __restrict__ wf = g_Wf + (long)(mt * 4 + wm) * 64 * 32;
        const uint32_t zbase = smem_u32(sm);
        float* Gs = (float*)sm;     // aliases h tile (barrier-guarded)

        const int jl = tid & 15;
        const int brow = tid >> 4;
        const int jg = mt * 16 + jl;
        float c_reg[4] = {0.f, 0.f, 0.f, 0.f};

        for (int t = 0; t < TT; ++t) {
            const int par = t & 1, nxt = par ^ 1;
            const __half* hp = g_h[par];

            // ONE parallel wait: all 32 producer flags + gx ring
            if (t > 0 && tid < 32) {
                volatile unsigned* f = &g_flag[nt][tid];
                while (*f < (unsigned)t) { }
            }
            if (tid == 32) {
                volatile unsigned* r = &sR;
                while (*r <= (unsigned)t) { }
            }
            BAR(1);

            // issue all h staging: 2 commit groups (cols 0-255, 256-511)
            #pragma unroll
            for (int gb = 0; gb < 4; ++gb) {
                #pragma unroll
                for (int it = 0; it < 4; ++it) {
                    int i2 = tid + it * 256;
                    int r = i2 >> 4, k8 = gb * 16 + (i2 & 15);
                    const __half* src = hp + (long)(b0 + r) * HH + k8 * 8;
                    CPASYNC16(zbase + r * PH + k8 * 16, src);
                }
                if (gb == 1 || gb == 3) CPCOMMIT();
            }

            // acc init from gx ring
            float acc[4][4];
            {
                const float* gq = (const float*)(sm + GXR_OFF + (t & 1) * GXSLOT);
                #pragma unroll
                for (int n2 = 0; n2 < 4; ++n2) {
                    const int col = nb + n2 * 8 + 2 * c4;
                    const int row = wm * 16 + g;
                    acc[n2][0] = gq[row * 68 + col];
                    acc[n2][1] = gq[row * 68 + col + 1];
                    acc[n2][2] = gq[(row + 8) * 68 + col];
                    acc[n2][3] = gq[(row + 8) * 68 + col + 1];
                }
            }
            BAR(1);
            if (tid == 0) *(volatile unsigned*)&sC = (unsigned)(t + 1);

            #pragma unroll
            for (int half = 0; half < 2; ++half) {
                if (half == 0) CPWAIT(1); else CPWAIT(0);
                BAR(1);
                #pragma unroll
                for (int kc2 = 0; kc2 < 4; ++kc2) {
                    const int kc = half * 4 + kc2;
                    const uint4* wfb = wf + (long)((kc + 8) * 4) * 32;
                    #pragma unroll
                    for (int ks = 0; ks < 4; ++ks) {
                        uint4 Ah = __ldg(&wfb[ks * 32 + lane]);
                        const int koff = kc * 128 + ks * 32 + c4 * 4;
                        #pragma unroll
                        for (int n2 = 0; n2 < 4; ++n2) {
                            const int base = (nb + n2 * 8 + g) * PH + koff;
                            unsigned bh0 = *(const unsigned*)(sm + base);
                            unsigned bh1 = *(const unsigned*)(sm + base + 16);
                            MMA(acc[n2], Ah, bh0, bh1);
                        }
                    }
                }
            }
            BAR(1);

            // exchange gates (Gs aliases h tile; all B reads complete)
            #pragma unroll
            for (int n2 = 0; n2 < 4; ++n2) {
                const int col = nb + n2 * 8 + 2 * c4;
                const int row = wm * 16 + g;
                Gs[row * 68 + col] = acc[n2][0];
                Gs[row * 68 + col + 1] = acc[n2][1];
                Gs[(row + 8) * 68 + col] = acc[n2][2];
                Gs[(row + 8) * 68 + col + 1] = acc[n2][3];
            }
            BAR(1);

            // elementwise; publish h first, out stores after the flag
            float hq[4], cq[4];
            #pragma unroll
            for (int q = 0; q < 4; ++q) {
                const int b = brow + 16 * q;
                const float iv = Gs[(0 + jl) * 68 + b];
                const float fv = Gs[(16 + jl) * 68 + b];
                const float gv = Gs[(32 + jl) * 68 + b];
                const float ov = Gs[(48 + jl) * 68 + b];
                const float c = sig_fast(fv) * c_reg[q] + sig_fast(iv) * tanh_fast(gv);
                c_reg[q] = c; cq[q] = c;
                const float h = sig_fast(ov) * tanh_fast(c);
                hq[q] = h;
                g_h[nxt][(long)(b0 + b) * HH + jg] = __float2half_rn(h);
            }
            __threadfence();
            BAR(1);
            if (tid == 0) atomicExch(&g_flag[nt][mt], (unsigned)(t + 1));

            #pragma unroll
            for (int q = 0; q < 4; ++q) {
                const int b = brow + 16 * q;
                out[(long)(b0 + b) * (TT * HH) + (long)t * HH + jg] = hq[q];
                if (t == TT - 1) {
                    const long gi = (long)(b0 + b) * HH + jg;
                    out[(long)BB * TT * HH + gi] = hq[q];
                    out[(long)BB * TT * HH + (long)BB * HH + gi] = cq[q];
                }
            }
        }
    }
}

extern "C" void kernel_launch(void* const* d_in, const int* in_sizes, int n_in,
                              void* d_out, int out_size) {
    const float* x   = (const float*)d_in[0];
    const float* wih = (const float*)d_in[1];
    const float* whh = (const float*)d_in[2];
    const float* bih = (const float*)d_in[3];
    const float* bhh = (const float*)d_in[4];
    float* out = (float*)d_out;
    (void)in_sizes; (void)n_in; (void)out_size;
    cudaFuncSetAttribute(lstm_fused, cudaFuncAttributeMaxDynamicSharedMemorySize, SMEM_TOTAL);
    phase0<<<1024, 256>>>(wih, whh);
    phaseX<<<4096, 256>>>(x);
    lstm_fused<<<NCTA, 512, SMEM_TOTAL>>>(bih, bhh, out);
}

// round 17
// speedup vs baseline: 1.1053x; 1.1053x over previous
#include <cuda_runtime.h>
#include <cuda_fp16.h>
#include <stdint.h>
#include <math.h>

#define TT 512
#define BB 256
#define FF 512
#define HH 512
#define NCTA 128
#define ZP 160                     // x-staging pitch (row stride = 8 words mod 32)
#define PH 1056                    // h-tile pitch (row stride = 8 words mod 32)
#define HSZ (64 * PH)              // 67584
#define XS_OFF HSZ                 // 2 x 10240
#define GXR_OFF (XS_OFF + 20480)   // 88064
#define GXSLOT 17408               // 64*68*4
#define SMEM_TOTAL (GXR_OFF + 2 * GXSLOT)   // 122880

// W (fp16) in mma-fragment order: [mt 32][wm 4][kstep 64][lane 32] x uint4
__device__ uint4 g_Wf[32 * 4 * 64 * 32];
// x fp16, chunk blocks [t][nt][kc][64r][64c], k PAIR-INTERLEAVED within ksteps
__device__ uint8_t g_xs[512L * 4 * 8 * 8192];
__device__ __half g_h[2][BB * HH];   // k pair-interleaved within ksteps
__device__ unsigned g_flag[4][32];   // [nt][mt]: steps completed

__device__ __forceinline__ uint32_t smem_u32(const void* p) {
    uint32_t a;
    asm("{ .reg .u64 t; cvta.to.shared.u64 t, %1; cvt.u32.u64 %0, t; }" : "=r"(a) : "l"(p));
    return a;
}
__device__ __forceinline__ unsigned pack2h(float a, float b) {
    __half2 t; t.x = __float2half_rn(a); t.y = __float2half_rn(b);
    return *(unsigned*)&t;
}
__device__ __forceinline__ float sig_fast(float v) {
    return __fdividef(1.0f, 1.0f + __expf(-v));
}
__device__ __forceinline__ float tanh_fast(float v) {
    float e = __expf(-2.0f * fabsf(v));
    return copysignf(__fdividef(1.0f - e, 1.0f + e), v);
}

#define MMA(c, a, b0, b1) \
    asm volatile("mma.sync.aligned.m16n8k16.row.col.f32.f16.f16.f32 " \
        "{%0,%1,%2,%3}, {%4,%5,%6,%7}, {%8,%9}, {%0,%1,%2,%3};" \
        : "+f"((c)[0]), "+f"((c)[1]), "+f"((c)[2]), "+f"((c)[3]) \
        : "r"((a).x), "r"((a).y), "r"((a).z), "r"((a).w), "r"(b0), "r"(b1))

#define CPASYNC16(dst, src) \
    asm volatile("cp.async.cg.shared.global [%0], [%1], 16;" :: "r"(dst), "l"(src))
#define CPCOMMIT() asm volatile("cp.async.commit_group;" ::: "memory")
#define CPWAIT(n)  asm volatile("cp.async.wait_group %0;" :: "n"(n) : "memory")
#define BAR(id)    asm volatile("bar.sync %0, 256;" :: "r"(id) : "memory")

// ---- phase 0: W gather to fp16 fragment order; zero h0; reset flags ----
__global__ void phase0(const float* __restrict__ wih, const float* __restrict__ whh) {
    long id = (long)blockIdx.x * blockDim.x + threadIdx.x;
    long stride = (long)gridDim.x * blockDim.x;
    for (long i = id; i < 32L * 4 * 64 * 32; i += stride) {
        int lane = (int)(i & 31);
        int kstep = (int)((i >> 5) & 63);
        int wm = (int)((i >> 11) & 3);
        int mt = (int)(i >> 13);
        int g = lane >> 2, c4 = lane & 3;
        int ka = kstep * 16 + 2 * c4;
        float e[2][4];
        #pragma unroll
        for (int rr = 0; rr < 2; ++rr) {
            int r = wm * 16 + g + rr * 8;
            int orig = (r >> 4) * 512 + mt * 16 + (r & 15);
            #pragma unroll
            for (int kk = 0; kk < 4; ++kk) {
                int k = ka + (kk & 1) + (kk >> 1) * 8;
                e[rr][kk] = (k < 512) ? wih[(long)orig * 512 + k]
                                      : whh[(long)orig * 512 + k - 512];
            }
        }
        uint4 o;
        o.x = pack2h(e[0][0], e[0][1]);
        o.y = pack2h(e[1][0], e[1][1]);
        o.z = pack2h(e[0][2], e[0][3]);
        o.w = pack2h(e[1][2], e[1][3]);
        g_Wf[i] = o;
    }
    __half z = __float2half_rn(0.0f);
    for (long i = id; i < (long)BB * HH; i += stride) g_h[0][i] = z;
    if (id < 128) ((unsigned*)g_flag)[id] = 0;
}

// ---- phase X: x -> fp16, k pair-interleaved within each 16-el kstep ----
// output 16B block o8: positions [half*8 .. half*8+7] of kstep ks (ks=o8>>1, half=o8&1)
// contain orig k pairs (b,b+1),(b+8,b+9),(b+2,b+3),(b+10,b+11), b = half*4
// id bits: o8[0:3) r[3:9) kc[9:12) nt[12:14) t[14:...)
__global__ void phaseX(const float* __restrict__ x) {
    long stride = (long)gridDim.x * blockDim.x;
    for (long id = (long)blockIdx.x * blockDim.x + threadIdx.x;
         id < 8388608L; id += stride) {
        int o8 = (int)(id & 7);
        int r  = (int)((id >> 3) & 63);
        int kc = (int)((id >> 9) & 7);
        int nt = (int)((id >> 12) & 3);
        long t = id >> 14;
        int ks = o8 >> 1, half = o8 & 1;
        int korig = kc * 64 + ks * 16 + half * 4;
        const float* src = x + ((t * 256) + nt * 64 + r) * 512L + korig;
        float4 A = *(const float4*)src;
        float4 B = *(const float4*)(src + 8);
        uint4 o = make_uint4(pack2h(A.x, A.y), pack2h(B.x, B.y),
                             pack2h(A.z, A.w), pack2h(B.z, B.w));
        long blk = (t * 4 + nt) * 8 + kc;
        *(uint4*)(g_xs + blk * 8192 + r * 128 + o8 * 16) = o;
    }
}

// ---- fused persistent kernel: warps 0-7 recurrence, warps 8-15 gx producer ----
__global__ void __launch_bounds__(512, 1) lstm_fused(
    const float* __restrict__ bih,
    const float* __restrict__ bhh,
    float* __restrict__ out)
{
    extern __shared__ __align__(16) char sm[];
    __shared__ unsigned sR, sC;

    const int tid = threadIdx.x;
    const int mt = blockIdx.x >> 2;
    const int nt = blockIdx.x & 3;
    const int b0 = nt * 64;

    if (tid == 0) { sR = 0; sC = 0; }
    __syncthreads();

    if (tid >= 256) {
        // ================= PRODUCER: gx[t] = x_t * Wih^T + biases =================
        const int ptid = tid - 256;
        const int lane = ptid & 31;
        const int g = lane >> 2, c4 = lane & 3;
        const int wid = ptid >> 5;
        const int wm = wid >> 1, wn = wid & 1;
        const int nb = wn * 32;
        const uint4* __restrict__ wf = g_Wf + (long)(mt * 4 + wm) * 64 * 32;

        const int r0 = wm * 16 + g, r1 = r0 + 8;
        const int o0 = (r0 >> 4) * 512 + mt * 16 + (r0 & 15);
        const int o1 = (r1 >> 4) * 512 + mt * 16 + (r1 & 15);
        const float b_r0 = bih[o0] + bhh[o0];
        const float b_r1 = bih[o1] + bhh[o1];

        for (int t = 0; t < TT; ++t) {
            if (ptid == 0) {
                volatile unsigned* c = &sC;
                while (*c + 2u <= (unsigned)t) { }
            }
            BAR(2);

            float acc[4][4];
            #pragma unroll
            for (int n2 = 0; n2 < 4; ++n2) {
                acc[n2][0] = b_r0; acc[n2][1] = b_r0;
                acc[n2][2] = b_r1; acc[n2][3] = b_r1;
            }
            const uint8_t* xb = g_xs + (((long)t * 4 + nt) * 8) * 8192;

            #pragma unroll
            for (int it = 0; it < 2; ++it) {
                int i = ptid + it * 256;
                int r = i >> 3, k8 = i & 7;
                uint4 v = __ldcg((const uint4*)(xb + r * 128 + k8 * 16));
                *(uint4*)(sm + XS_OFF + r * ZP + k8 * 16) = v;
            }
            BAR(2);

            for (int kc = 0; kc < 8; ++kc) {
                const int buf = kc & 1;
                uint4 pf[2];
                if (kc < 7) {
                    const uint8_t* xc = xb + (kc + 1) * 8192;
                    #pragma unroll
                    for (int it = 0; it < 2; ++it) {
                        int i = ptid + it * 256;
                        int r = i >> 3, k8 = i & 7;
                        pf[it] = __ldcg((const uint4*)(xc + r * 128 + k8 * 16));
                    }
                }
                {
                    const uint4* wfb = wf + (long)(kc * 4) * 32;
                    const char* zb0 = sm + XS_OFF + buf * 10240;
                    #pragma unroll
                    for (int ks = 0; ks < 4; ++ks) {
                        uint4 Ah = __ldg(&wfb[ks * 32 + lane]);
                        const char* zh = zb0 + ks * 32 + c4 * 8;
                        #pragma unroll
                        for (int n2 = 0; n2 < 4; ++n2) {
                            uint2 bp = *(const uint2*)(zh + (nb + n2 * 8 + g) * ZP);
                            MMA(acc[n2], Ah, bp.x, bp.y);
                        }
                    }
                }
                if (kc < 7) {
                    char* d = sm + XS_OFF + (buf ^ 1) * 10240;
                    #pragma unroll
                    for (int it = 0; it < 2; ++it) {
                        int i = ptid + it * 256;
                        int r = i >> 3, k8 = i & 7;
                        *(uint4*)(d + r * ZP + k8 * 16) = pf[it];
                    }
                }
                BAR(2);
            }

            float* gq = (float*)(sm + GXR_OFF + (t & 1) * GXSLOT);
            #pragma unroll
            for (int n2 = 0; n2 < 4; ++n2) {
                const int col = nb + n2 * 8 + 2 * c4;
                const int row = wm * 16 + g;
                gq[row * 68 + col] = acc[n2][0];
                gq[row * 68 + col + 1] = acc[n2][1];
                gq[(row + 8) * 68 + col] = acc[n2][2];
                gq[(row + 8) * 68 + col + 1] = acc[n2][3];
            }
            BAR(2);
            if (ptid == 0) *(volatile unsigned*)&sR = (unsigned)(t + 1);
        }
    } else {
        // ================= CONSUMER: recurrence =================
        const int wid = tid >> 5;
        const int lane = tid & 31;
        const int g = lane >> 2, c4 = lane & 3;
        const int wm = wid >> 1, wn = wid & 1;
        const int nb = wn * 32;
        const uint4* __restrict__ wf = g_Wf + (long)(mt * 4 + wm) * 64 * 32;
        const uint32_t zbase = smem_u32(sm);
        float* Gs = (float*)sm;     // aliases h tile (barrier-guarded)

        const int jl = tid & 15;
        const int brow = tid >> 4;
        const int jg = mt * 16 + jl;
        // pair-interleaved position of jl within its kstep (for g_h publish)
        const int jlp = (jl < 8) ? ((jl >> 1) * 4 + (jl & 1))
                                 : (((jl - 8) >> 1) * 4 + 2 + (jl & 1));
        const int jgp = mt * 16 + jlp;
        float c_reg[4] = {0.f, 0.f, 0.f, 0.f};

        for (int t = 0; t < TT; ++t) {
            const int par = t & 1, nxt = par ^ 1;
            const __half* hp = g_h[par];

            // ONE parallel wait: all 32 producer flags (lanes of warp0) + gx ring
            if (t > 0 && tid < 32) {
                volatile unsigned* f = &g_flag[nt][tid];
                while (*f < (unsigned)t) { }
            }
            if (tid == 32) {
                volatile unsigned* r = &sR;
                while (*r <= (unsigned)t) { }
            }
            BAR(1);

            // issue ALL 4 h groups back-to-back (pipelined commits)
            #pragma unroll
            for (int gb = 0; gb < 4; ++gb) {
                #pragma unroll
                for (int it = 0; it < 4; ++it) {
                    int i2 = tid + it * 256;
                    int r = i2 >> 4, k8 = gb * 16 + (i2 & 15);
                    const __half* src = hp + (long)(b0 + r) * HH + k8 * 8;
                    CPASYNC16(zbase + r * PH + k8 * 16, src);
                }
                CPCOMMIT();
            }

            // acc init from gx ring
            float acc[4][4];
            {
                const float* gq = (const float*)(sm + GXR_OFF + (t & 1) * GXSLOT);
                #pragma unroll
                for (int n2 = 0; n2 < 4; ++n2) {
                    const int col = nb + n2 * 8 + 2 * c4;
                    const int row = wm * 16 + g;
                    acc[n2][0] = gq[row * 68 + col];
                    acc[n2][1] = gq[row * 68 + col + 1];
                    acc[n2][2] = gq[(row + 8) * 68 + col];
                    acc[n2][3] = gq[(row + 8) * 68 + col + 1];
                }
            }
            BAR(1);
            if (tid == 0) *(volatile unsigned*)&sC = (unsigned)(t + 1);

            #pragma unroll
            for (int half = 0; half < 4; ++half) {
                if (half == 0) CPWAIT(3);
                else if (half == 1) CPWAIT(2);
                else if (half == 2) CPWAIT(1);
                else CPWAIT(0);
                BAR(1);
                #pragma unroll
                for (int kc2 = 0; kc2 < 2; ++kc2) {
                    const int kc = half * 2 + kc2;
                    const uint4* wfb = wf + (long)((kc + 8) * 4) * 32;
                    #pragma unroll
                    for (int ks = 0; ks < 4; ++ks) {
                        uint4 Ah = __ldg(&wfb[ks * 32 + lane]);
                        const int koff = kc * 128 + ks * 32 + c4 * 8;
                        #pragma unroll
                        for (int n2 = 0; n2 < 4; ++n2) {
                            uint2 bp = *(const uint2*)(sm + (nb + n2 * 8 + g) * PH + koff);
                            MMA(acc[n2], Ah, bp.x, bp.y);
                        }
                    }
                }
            }
            BAR(1);

            // exchange gates (Gs aliases h tile; all B reads complete)
            #pragma unroll
            for (int n2 = 0; n2 < 4; ++n2) {
                const int col = nb + n2 * 8 + 2 * c4;
                const int row = wm * 16 + g;
                Gs[row * 68 + col] = acc[n2][0];
                Gs[row * 68 + col + 1] = acc[n2][1];
                Gs[(row + 8) * 68 + col] = acc[n2][2];
                Gs[(row + 8) * 68 + col + 1] = acc[n2][3];
            }
            BAR(1);

            // elementwise; publish h (pair-interleaved position) first
            float hq[4], cq[4];
            #pragma unroll
            for (int q = 0; q < 4; ++q) {
                const int b = brow + 16 * q;
                const float iv = Gs[(0 + jl) * 68 + b];
                const float fv = Gs[(16 + jl) * 68 + b];
                const float gv = Gs[(32 + jl) * 68 + b];
                const float ov = Gs[(48 + jl) * 68 + b];
                const float c = sig_fast(fv) * c_reg[q] + sig_fast(iv) * tanh_fast(gv);
                c_reg[q] = c; cq[q] = c;
                const float h = sig_fast(ov) * tanh_fast(c);
                hq[q] = h;
                g_h[nxt][(long)(b0 + b) * HH + jgp] = __float2half_rn(h);
            }
            BAR(1);
            if (tid == 0) {
                __threadfence();     // single-thread fence after BAR orders all stores
                atomicExch(&g_flag[nt][mt], (unsigned)(t + 1));
            }

            #pragma unroll
            for (int q = 0; q < 4; ++q) {
                const int b = brow + 16 * q;
                out[(long)(b0 + b) * (TT * HH) + (long)t * HH + jg] = hq[q];
                if (t == TT - 1) {
                    const long gi = (long)(b0 + b) * HH + jg;
                    out[(long)BB * TT * HH + gi] = hq[q];
                    out[(long)BB * TT * HH + (long)BB * HH + gi] = cq[q];
                }
            }
        }
    }
}

extern "C" void kernel_launch(void* const* d_in, const int* in_sizes, int n_in,
                              void* d_out, int out_size) {
    const float* x   = (const float*)d_in[0];
    const float* wih = (const float*)d_in[1];
    const float* whh = (const float*)d_in[2];
    const float* bih = (const float*)d_in[3];
    const float* bhh = (const float*)d_in[4];
    float* out = (float*)d_out;
    (void)in_sizes; (void)n_in; (void)out_size;
    cudaFuncSetAttribute(lstm_fused, cudaFuncAttributeMaxDynamicSharedMemorySize, SMEM_TOTAL);
    phase0<<<1024, 256>>>(wih, whh);
    phaseX<<<4096, 256>>>(x);
    lstm_fused<<<NCTA, 512, SMEM_TOTAL>>>(bih, bhh, out);
}